// round 8
// baseline (speedup 1.0000x reference)
#include <cuda_runtime.h>
#include <cuda_fp16.h>
#include <cstdint>
#include <cstddef>
#include <cstring>

// ---------------------------------------------------------------------------
#define BATCH   32768
#define LATENT  512
#define NSUP    256
#define NSUB    1024
#define NOUT    200
#define BROWS   1536              // fused B rows: [sub | M2(pad to 256) | M1(pad to 256)]
#define M2BASE  1024
#define M1BASE  1280
#define INF_KEY 0xFFFFFFFFu

// main GEMM tiling (fp16 operands, fp16 window accum -> fp32)
#define MTILE    128
#define NTILE    256
#define NTHREADS 512
#define KC       32                        // k-chunk in halves
#define NSTAGES  4
#define KITERS   (LATENT / KC)             // 16
#define ROWSTR_H 40                        // smem row stride in halves (80B, conflict-free)
#define ABYTES   (MTILE * ROWSTR_H * 2)    // 10240
#define BBYTES   (NTILE * ROWSTR_H * 2)    // 20480
#define STAGE_BYTES (ABYTES + BBYTES)      // 30720
#define SMEM_DYN (NSTAGES * STAGE_BYTES)   // 122880

// ---------------------------- device scratch --------------------------------
__device__ __half   g_Ah[BATCH * LATENT];    // x in fp16
__device__ __half   g_Bh[BROWS * LATENT];    // fused B in fp16, [N][K] row-major
__device__ float    g_xx[BATCH];
__device__ float    g_yysub[NSUB];
__device__ float    g_yysup[NSUP];
__device__ float    g_s1[NOUT], g_c1[NOUT], g_s2[NOUT], g_c2[NOUT];
__device__ unsigned g_rowmin[BATCH];
__device__ unsigned g_colmin[NSUB];
__device__ unsigned g_ssrow[NSUP];
__device__ unsigned g_sscol[NSUB];

// order-preserving float <-> uint keys
__device__ __forceinline__ unsigned fkey(float f) {
    unsigned u = __float_as_uint(f);
    return (u & 0x80000000u) ? ~u : (u | 0x80000000u);
}
__device__ __forceinline__ float funkey(unsigned k) {
    return __uint_as_float((k & 0x80000000u) ? (k & 0x7FFFFFFFu) : ~k);
}

// ---------------------------- PTX helpers -----------------------------------
__device__ __forceinline__ uint32_t smem_u32(const void* p) {
    uint32_t a;
    asm("{ .reg .u64 t; cvta.to.shared.u64 t, %1; cvt.u32.u64 %0, t; }"
        : "=r"(a) : "l"(p));
    return a;
}
__device__ __forceinline__ void cp16(uint32_t dst, const void* src) {
    asm volatile("cp.async.cg.shared.global [%0], [%1], 16;" :: "r"(dst), "l"(src));
}
#define CP_COMMIT() asm volatile("cp.async.commit_group;" ::: "memory")
#define CP_WAIT3()  asm volatile("cp.async.wait_group 3;"  ::: "memory")

__device__ __forceinline__ void ldsm4(uint32_t& r0, uint32_t& r1, uint32_t& r2, uint32_t& r3,
                                      uint32_t addr) {
    asm volatile("ldmatrix.sync.aligned.m8n8.x4.shared.b16 {%0,%1,%2,%3}, [%4];"
                 : "=r"(r0), "=r"(r1), "=r"(r2), "=r"(r3) : "r"(addr));
}
// fp16-accumulate variant: d/c are 2 regs (4 halves)
__device__ __forceinline__ void mma16816h(uint32_t* d, const uint32_t* a, const uint32_t* b) {
    asm volatile(
        "mma.sync.aligned.m16n8k16.row.col.f16.f16.f16.f16 "
        "{%0,%1}, {%2,%3,%4,%5}, {%6,%7}, {%0,%1};"
        : "+r"(d[0]), "+r"(d[1])
        : "r"(a[0]), "r"(a[1]), "r"(a[2]), "r"(a[3]), "r"(b[0]), "r"(b[1]));
}
__device__ __forceinline__ uint32_t h2u(__half2 h) {
    uint32_t u;
    memcpy(&u, &h, 4);
    return u;
}
__device__ __forceinline__ __half2 u2h(uint32_t u) {
    __half2 h;
    memcpy(&h, &u, 4);
    return h;
}

// ------------------------------- init ---------------------------------------
__global__ void init_kernel() {
    int t = blockIdx.x * blockDim.x + threadIdx.x;
    int n = gridDim.x * blockDim.x;
    for (int i = t; i < BATCH; i += n) g_rowmin[i] = INF_KEY;
    for (int i = t; i < NSUB;  i += n) g_colmin[i] = INF_KEY;
    for (int i = t; i < NSUP;  i += n) g_ssrow[i]  = INF_KEY;
    for (int i = t; i < NSUB;  i += n) g_sscol[i]  = INF_KEY;
    // zero pad rows [1224,1280) and [1480,1536)
    for (int i = t; i < 56 * LATENT; i += n) {
        int r = i / LATENT, k = i % LATENT;
        g_Bh[(size_t)(M2BASE + NOUT + r) * LATENT + k] = __float2half(0.f);
        g_Bh[(size_t)(M1BASE + NOUT + r) * LATENT + k] = __float2half(0.f);
    }
}

// -------------- fused row-norm + fp32->fp16 convert (warp per row) -----------
__global__ void prep_convert(const float* __restrict__ X, __half* __restrict__ dst,
                             float* __restrict__ nrm, int rows) {
    int w    = (blockIdx.x * blockDim.x + threadIdx.x) >> 5;
    int lane = threadIdx.x & 31;
    if (w >= rows) return;
    const float4* p = (const float4*)(X + (size_t)w * LATENT);
    __half* drow = dst + (size_t)w * LATENT;
    float s = 0.f;
#pragma unroll
    for (int i = 0; i < 4; i++) {
        float4 v = p[lane + 32 * i];
        s += v.x * v.x + v.y * v.y + v.z * v.z + v.w * v.w;
        uint2 u;
        u.x = h2u(__floats2half2_rn(v.x, v.y));
        u.y = h2u(__floats2half2_rn(v.z, v.w));
        *(uint2*)(drow + (lane + 32 * i) * 4) = u;
    }
#pragma unroll
    for (int o = 16; o; o >>= 1) s += __shfl_xor_sync(0xFFFFFFFFu, s, o);
    if (!lane) nrm[w] = s;
}

// ------------------------------ sup norms ------------------------------------
__global__ void norms_sup_kernel(const float* __restrict__ X) {
    int w    = (blockIdx.x * blockDim.x + threadIdx.x) >> 5;
    int lane = threadIdx.x & 31;
    if (w >= NSUP) return;
    const float4* p = (const float4*)(X + (size_t)w * LATENT);
    float s = 0.f;
#pragma unroll
    for (int i = 0; i < 4; i++) {
        float4 v = p[lane + 32 * i];
        s += v.x * v.x + v.y * v.y + v.z * v.z + v.w * v.w;
    }
#pragma unroll
    for (int o = 16; o; o >>= 1) s += __shfl_xor_sync(0xFFFFFFFFu, s, o);
    if (!lane) g_yysup[w] = s;
}

// ---------------- M build:  g_Bh[rowbase+o][k] = sum_j W[o][j] * P[j][k] ------
__global__ void buildM_kernel(const float* __restrict__ P, const float* __restrict__ W,
                              int J, int rowbase) {
    __shared__ float sP[64][17];   // [j][k]
    __shared__ float sW[16][65];   // [o][j]
    int k0 = blockIdx.x * 16, o0 = blockIdx.y * 16;
    int tx = threadIdx.x, ty = threadIdx.y;
    int tid = ty * 16 + tx;
    float acc = 0.f;
    for (int j0 = 0; j0 < J; j0 += 64) {
        for (int i = tid; i < 64 * 16; i += 256) {
            int jj = i / 16, kk = i % 16;
            sP[jj][kk] = P[(size_t)(j0 + jj) * LATENT + k0 + kk];
        }
        for (int i = tid; i < 16 * 64; i += 256) {
            int oo = i / 64, jj = i % 64;
            int o = o0 + oo;
            sW[oo][jj] = (o < NOUT) ? W[(size_t)o * J + j0 + jj] : 0.f;
        }
        __syncthreads();
#pragma unroll 16
        for (int jj = 0; jj < 64; jj++) acc += sP[jj][tx] * sW[ty][jj];
        __syncthreads();
    }
    if (o0 + ty < NOUT)
        g_Bh[(size_t)(rowbase + o0 + ty) * LATENT + k0 + tx] = __float2half_rn(acc);
}

// ------------- s/c vectors ----------------------------------------------------
__global__ void svec_kernel(const float* __restrict__ W1, const float* __restrict__ b1,
                            const float* __restrict__ W2, const float* __restrict__ b2) {
    int w = (blockIdx.x * blockDim.x + threadIdx.x) >> 5;
    int lane = threadIdx.x & 31;
    if (w >= 2 * NOUT) return;
    const float *W, *b, *yy;
    float *s, *c;
    int J, o;
    if (w < NOUT) { o = w;        W = W1; b = b1; yy = g_yysup; s = g_s1; c = g_c1; J = NSUP; }
    else          { o = w - NOUT; W = W2; b = b2; yy = g_yysub; s = g_s2; c = g_c2; J = NSUB; }
    float sw = 0.f, cy = 0.f;
    for (int j = lane; j < J; j += 32) {
        float wv = W[(size_t)o * J + j];
        sw += wv;
        cy += yy[j] * wv;
    }
#pragma unroll
    for (int off = 16; off; off >>= 1) {
        sw += __shfl_xor_sync(0xFFFFFFFFu, sw, off);
        cy += __shfl_xor_sync(0xFFFFFFFFu, cy, off);
    }
    if (!lane) { s[o] = sw; c[o] = b[o] + cy; }
}

// ------------------- super-sub distances: r3/r4 min sources -------------------
// grid (32, 4): x = 8 sup rows, y = 256-wide sub slice; one j per thread.
__global__ void supersub_kernel(const float* __restrict__ sup, const float* __restrict__ sub) {
    __shared__ float4 sp[8][LATENT / 4];
    __shared__ float  red[256];
    int i0 = blockIdx.x * 8, tid = threadIdx.x;
    int j = blockIdx.y * 256 + tid;
    for (int t = tid; t < 8 * (LATENT / 4); t += 256) {
        int r = t / (LATENT / 4), k = t % (LATENT / 4);
        sp[r][k] = ((const float4*)(sup + (size_t)(i0 + r) * LATENT))[k];
    }
    __syncthreads();

    const float4* pj = (const float4*)(sub + (size_t)j * LATENT);
    float dot[8];
#pragma unroll
    for (int r = 0; r < 8; r++) dot[r] = 0.f;
    for (int k = 0; k < LATENT / 4; k++) {
        float4 p = pj[k];
#pragma unroll
        for (int r = 0; r < 8; r++) {
            float4 a = sp[r][k];
            dot[r] += a.x * p.x + a.y * p.y + a.z * p.z + a.w * p.w;
        }
    }
    float yj = g_yysub[j], cmin = 3.4e38f;
    float dr[8];
#pragma unroll
    for (int r = 0; r < 8; r++) {
        dr[r] = g_yysup[i0 + r] - 2.f * dot[r] + yj;
        cmin = fminf(cmin, dr[r]);
    }
    atomicMin(&g_sscol[j], fkey(cmin));
#pragma unroll
    for (int r = 0; r < 8; r++) {
        red[tid] = dr[r];
        __syncthreads();
        for (int s = 128; s; s >>= 1) {
            if (tid < s) red[tid] = fminf(red[tid], red[tid + s]);
            __syncthreads();
        }
        if (tid == 0) atomicMin(&g_ssrow[i0 + r], fkey(red[0]));
        __syncthreads();
    }
}

// ------------------------------- main GEMM (mma.sync fp16, f16 acc) ----------
// grid (6, 256). 512 threads = 16 warps: wm = wid&3 (rows 32), wn = wid>>2 (cols 64).
// Warp tile 32x64. fp16 accumulators per 64-K window, promoted to fp32.
__device__ __forceinline__ void load_chunk(uint32_t astage, const __half* Abase,
                                           const __half* Bbase, int k0, int tid) {
    {                                        // A: 128 rows x 4 x 16B = 512 segs
        int row = tid >> 2, q = tid & 3;
        cp16(astage + row * (ROWSTR_H * 2) + q * 16,
             Abase + (size_t)row * LATENT + k0 + q * 8);
    }
    uint32_t bstage = astage + ABYTES;
#pragma unroll
    for (int t = 0; t < 2; t++) {            // B: 256 rows x 4 x 16B = 1024 segs
        int seg = tid + t * NTHREADS;
        int row = seg >> 2, q = seg & 3;
        cp16(bstage + row * (ROWSTR_H * 2) + q * 16,
             Bbase + (size_t)row * LATENT + k0 + q * 8);
    }
}

__global__ __launch_bounds__(NTHREADS) void gemm_tc(
    float* __restrict__ outSub, float* __restrict__ outSup)
{
    extern __shared__ char dyn[];
    __shared__ unsigned s_row[MTILE], s_col[NTILE];
    __shared__ float sh_c0[NTILE], sh_c1[NTILE];

    const int tid = threadIdx.x;
    const int wid = tid >> 5, lane = tid & 31;
    const int grp = lane >> 2, tig = lane & 3;
    const int wm = wid & 3, wn = wid >> 2;
    const int bn = blockIdx.x, bm = blockIdx.y;
    const uint32_t dynb = smem_u32(dyn);

    if (tid < MTILE) s_row[tid] = INF_KEY;
    if (tid < NTILE) {
        s_col[tid] = INF_KEY;
        if (bn < 4) {
            sh_c0[tid] = g_yysub[bn * NTILE + tid];
        } else {
            const float* sv = (bn == 4) ? g_s2 : g_s1;
            const float* cv = (bn == 4) ? g_c2 : g_c1;
            sh_c0[tid] = (tid < NOUT) ? sv[tid] : 0.f;
            sh_c1[tid] = (tid < NOUT) ? cv[tid] : 0.f;
        }
    }

    const __half* Abase = g_Ah + (size_t)bm * MTILE * LATENT;
    const __half* Bbase = g_Bh + (size_t)bn * NTILE * LATENT;

    // prologue: stages 0..2
#pragma unroll
    for (int s = 0; s < NSTAGES - 1; s++) {
        load_chunk(dynb + s * STAGE_BYTES, Abase, Bbase, s * KC, tid);
        CP_COMMIT();
    }

    float acc[2][8][4];
    uint32_t acch[2][8][2];
#pragma unroll
    for (int mf = 0; mf < 2; mf++)
#pragma unroll
        for (int nf = 0; nf < 8; nf++) {
#pragma unroll
            for (int e = 0; e < 4; e++) acc[mf][nf][e] = 0.f;
            acch[mf][nf][0] = 0u;
            acch[mf][nf][1] = 0u;
        }

    // ldmatrix lane address offsets (in halves)
    const int a_moff = ((lane >> 3) & 1) * 8 + (lane & 7);
    const int a_koff = (lane >> 4) * 8;
    const int b_noff = (lane >> 4) * 8 + (lane & 7);
    const int b_koff = ((lane >> 3) & 1) * 8;

    for (int k = 0; k < KITERS; k++) {
        if (k + NSTAGES - 1 < KITERS)
            load_chunk(dynb + ((k + NSTAGES - 1) & (NSTAGES - 1)) * STAGE_BYTES,
                       Abase, Bbase, (k + NSTAGES - 1) * KC, tid);
        CP_COMMIT();
        CP_WAIT3();
        __syncthreads();

        const uint32_t As = dynb + (k & (NSTAGES - 1)) * STAGE_BYTES;
        const uint32_t Bs = As + ABYTES;
#pragma unroll
        for (int ks = 0; ks < 2; ks++) {
            const int kb = ks * 16;
            uint32_t a[2][4], b[8][2];
            {
                uint32_t addr = As + (uint32_t)(((wm * 32 + a_moff) * ROWSTR_H
                                                 + kb + a_koff) * 2);
                ldsm4(a[0][0], a[0][1], a[0][2], a[0][3], addr);
                addr = As + (uint32_t)(((wm * 32 + 16 + a_moff) * ROWSTR_H
                                         + kb + a_koff) * 2);
                ldsm4(a[1][0], a[1][1], a[1][2], a[1][3], addr);
            }
#pragma unroll
            for (int nfp = 0; nfp < 4; nfp++) {
                uint32_t addr = Bs + (uint32_t)(((wn * 64 + nfp * 16 + b_noff) * ROWSTR_H
                                                 + kb + b_koff) * 2);
                ldsm4(b[2 * nfp][0], b[2 * nfp][1], b[2 * nfp + 1][0], b[2 * nfp + 1][1], addr);
            }
#pragma unroll
            for (int mf = 0; mf < 2; mf++)
#pragma unroll
                for (int nf = 0; nf < 8; nf++)
                    mma16816h(acch[mf][nf], a[mf], b[nf]);
        }
        // promote fp16 window accumulators to fp32 every 2 k-iters (64 K elems)
        if ((k & 1) == 1) {
#pragma unroll
            for (int mf = 0; mf < 2; mf++)
#pragma unroll
                for (int nf = 0; nf < 8; nf++) {
                    float2 lo = __half22float2(u2h(acch[mf][nf][0]));
                    float2 hi = __half22float2(u2h(acch[mf][nf][1]));
                    acc[mf][nf][0] += lo.x;
                    acc[mf][nf][1] += lo.y;
                    acc[mf][nf][2] += hi.x;
                    acc[mf][nf][3] += hi.y;
                    acch[mf][nf][0] = 0u;
                    acch[mf][nf][1] = 0u;
                }
        }
        __syncthreads();
    }

    // ------------------------------ epilogue ---------------------------------
    float xr[2][2];
#pragma unroll
    for (int mf = 0; mf < 2; mf++)
#pragma unroll
        for (int h = 0; h < 2; h++)
            xr[mf][h] = g_xx[bm * MTILE + wm * 32 + mf * 16 + h * 8 + grp];

    if (bn < 4) {                                      // distance region
#pragma unroll
        for (int mf = 0; mf < 2; mf++)
#pragma unroll
            for (int nf = 0; nf < 8; nf++) {
                float y0 = sh_c0[wn * 64 + nf * 8 + tig * 2];
                float y1 = sh_c0[wn * 64 + nf * 8 + tig * 2 + 1];
                acc[mf][nf][0] = xr[mf][0] - 2.f * acc[mf][nf][0] + y0;
                acc[mf][nf][1] = xr[mf][0] - 2.f * acc[mf][nf][1] + y1;
                acc[mf][nf][2] = xr[mf][1] - 2.f * acc[mf][nf][2] + y0;
                acc[mf][nf][3] = xr[mf][1] - 2.f * acc[mf][nf][3] + y1;
            }
        // row mins
#pragma unroll
        for (int mf = 0; mf < 2; mf++)
#pragma unroll
            for (int h = 0; h < 2; h++) {
                float m = 3.4e38f;
#pragma unroll
                for (int nf = 0; nf < 8; nf++)
                    m = fminf(m, fminf(acc[mf][nf][h * 2], acc[mf][nf][h * 2 + 1]));
                m = fminf(m, __shfl_xor_sync(0xFFFFFFFFu, m, 1));
                m = fminf(m, __shfl_xor_sync(0xFFFFFFFFu, m, 2));
                if (tig == 0)
                    atomicMin(&s_row[wm * 32 + mf * 16 + h * 8 + grp], fkey(m));
            }
        // col mins
#pragma unroll
        for (int nf = 0; nf < 8; nf++)
#pragma unroll
            for (int c = 0; c < 2; c++) {
                float m = 3.4e38f;
#pragma unroll
                for (int mf = 0; mf < 2; mf++)
                    m = fminf(m, fminf(acc[mf][nf][c], acc[mf][nf][2 + c]));
                m = fminf(m, __shfl_xor_sync(0xFFFFFFFFu, m, 4));
                m = fminf(m, __shfl_xor_sync(0xFFFFFFFFu, m, 8));
                m = fminf(m, __shfl_xor_sync(0xFFFFFFFFu, m, 16));
                if (grp == 0)
                    atomicMin(&s_col[wn * 64 + nf * 8 + tig * 2 + c], fkey(m));
            }
        __syncthreads();
        if (tid < MTILE) atomicMin(&g_rowmin[bm * MTILE + tid], s_row[tid]);
        if (tid < NTILE) atomicMin(&g_colmin[bn * NTILE + tid], s_col[tid]);
    } else {                                           // linear output regions
        float* outp = (bn == 4) ? outSub : outSup;
#pragma unroll
        for (int mf = 0; mf < 2; mf++)
#pragma unroll
            for (int h = 0; h < 2; h++) {
                int row = bm * MTILE + wm * 32 + mf * 16 + h * 8 + grp;
                float xv = xr[mf][h];
#pragma unroll
                for (int nf = 0; nf < 8; nf++) {
                    int o = wn * 64 + nf * 8 + tig * 2;
                    if (o < NOUT) {
                        float2 v;
                        v.x = xv * sh_c0[o]     - 2.f * acc[mf][nf][h * 2]     + sh_c1[o];
                        v.y = xv * sh_c0[o + 1] - 2.f * acc[mf][nf][h * 2 + 1] + sh_c1[o + 1];
                        *(float2*)(outp + (size_t)row * NOUT + o) = v;
                    }
                }
            }
    }
}

// ------------------------------- finalize ------------------------------------
__global__ void finalize_kernel(float* __restrict__ out4) {
    __shared__ float red[1024];
    int tid = threadIdx.x;
    float r1 = 0.f, r2 = 0.f, r3 = 0.f;

    red[tid] = funkey(g_colmin[tid]);
    __syncthreads();
    for (int s = 512; s > 0; s >>= 1) { if (tid < s) red[tid] += red[tid + s]; __syncthreads(); }
    if (tid == 0) r1 = red[0] * (1.f / NSUB);
    __syncthreads();

    float acc = 0.f;
    for (int i = tid; i < BATCH; i += 1024) acc += funkey(g_rowmin[i]);
    red[tid] = acc;
    __syncthreads();
    for (int s = 512; s > 0; s >>= 1) { if (tid < s) red[tid] += red[tid + s]; __syncthreads(); }
    if (tid == 0) r2 = red[0] * (1.f / BATCH);
    __syncthreads();

    red[tid] = (tid < NSUP) ? funkey(g_ssrow[tid]) : 0.f;
    __syncthreads();
    for (int s = 512; s > 0; s >>= 1) { if (tid < s) red[tid] += red[tid + s]; __syncthreads(); }
    if (tid == 0) r3 = red[0] * (1.f / NSUP);
    __syncthreads();

    red[tid] = funkey(g_sscol[tid]);
    __syncthreads();
    for (int s = 512; s > 0; s >>= 1) { if (tid < s) red[tid] += red[tid + s]; __syncthreads(); }
    if (tid == 0) {
        out4[0] = r1; out4[1] = r2; out4[2] = r3;
        out4[3] = red[0] * (1.f / NSUB);
    }
}

// ------------------------------- launcher ------------------------------------
extern "C" void kernel_launch(void* const* d_in, const int* in_sizes, int n_in,
                              void* d_out, int out_size) {
    const float* x   = (const float*)d_in[0];
    const float* sup = (const float*)d_in[1];
    const float* sub = (const float*)d_in[2];
    const float* W1  = (const float*)d_in[3];
    const float* b1  = (const float*)d_in[4];
    const float* W2  = (const float*)d_in[5];
    const float* b2  = (const float*)d_in[6];
    float* out    = (float*)d_out;
    float* outSub = out;
    float* outSup = out + (size_t)BATCH * NOUT;
    float* out4   = out + (size_t)2 * BATCH * NOUT;

    cudaFuncSetAttribute(gemm_tc, cudaFuncAttributeMaxDynamicSharedMemorySize, SMEM_DYN);

    __half *dAh = nullptr, *dBh = nullptr;
    float *dxx = nullptr, *dyysub = nullptr;
    cudaGetSymbolAddress((void**)&dAh, g_Ah);
    cudaGetSymbolAddress((void**)&dBh, g_Bh);
    cudaGetSymbolAddress((void**)&dxx, g_xx);
    cudaGetSymbolAddress((void**)&dyysub, g_yysub);

    init_kernel<<<128, 256>>>();

    prep_convert<<<(BATCH * 32 + 255) / 256, 256>>>(x,   dAh, dxx,    BATCH);
    prep_convert<<<(NSUB  * 32 + 255) / 256, 256>>>(sub, dBh, dyysub, NSUB);
    norms_sup_kernel<<<(NSUP * 32 + 255) / 256, 256>>>(sup);

    buildM_kernel<<<dim3(LATENT / 16, (NOUT + 15) / 16), dim3(16, 16)>>>(sub, W2, NSUB, M2BASE);
    buildM_kernel<<<dim3(LATENT / 16, (NOUT + 15) / 16), dim3(16, 16)>>>(sup, W1, NSUP, M1BASE);

    svec_kernel<<<(2 * NOUT * 32 + 255) / 256, 256>>>(W1, b1, W2, b2);
    supersub_kernel<<<dim3(NSUP / 8, 4), 256>>>(sup, sub);

    gemm_tc<<<dim3(BROWS / NTILE, BATCH / MTILE), NTHREADS, SMEM_DYN>>>(outSub, outSup);

    finalize_kernel<<<1, 1024>>>(out4);
}

// round 9
// speedup vs baseline: 1.2056x; 1.2056x over previous
#include <cuda_runtime.h>
#include <cuda_fp16.h>
#include <cstdint>
#include <cstddef>
#include <cstring>

// ---------------------------------------------------------------------------
#define BATCH   32768
#define LATENT  512
#define NSUP    256
#define NSUB    1024
#define NOUT    200
#define BROWS   1536              // fused B rows: [sub | M2(pad to 256) | M1(pad to 256)]
#define M2BASE  1024
#define M1BASE  1280
#define INF_KEY 0xFFFFFFFFu

// main GEMM tiling (fp16 operands, fp32 accum)
#define MTILE    128
#define NTILE    256
#define NTHREADS 512
#define KC       64                        // k-chunk in halves (128B payload per row)
#define NSTAGES  3
#define KITERS   (LATENT / KC)             // 8
#define ROWSTR_H 72                        // smem row stride in halves (144B, conflict-free)
#define ABYTES   (MTILE * ROWSTR_H * 2)    // 18432
#define BBYTES   (NTILE * ROWSTR_H * 2)    // 36864
#define STAGE_BYTES (ABYTES + BBYTES)      // 55296
#define SMEM_DYN (NSTAGES * STAGE_BYTES)   // 165888

// ---------------------------- device scratch --------------------------------
__device__ __half   g_Ah[BATCH * LATENT];    // x in fp16
__device__ __half   g_Bh[BROWS * LATENT];    // fused B in fp16, [N][K] row-major
__device__ float    g_xx[BATCH];
__device__ float    g_yysub[NSUB];
__device__ float    g_yysup[NSUP];
__device__ float    g_s1[NOUT], g_c1[NOUT], g_s2[NOUT], g_c2[NOUT];
__device__ unsigned g_rowmin[BATCH];
__device__ unsigned g_colmin[NSUB];
__device__ unsigned g_ssrow[NSUP];
__device__ unsigned g_sscol[NSUB];

// order-preserving float <-> uint keys
__device__ __forceinline__ unsigned fkey(float f) {
    unsigned u = __float_as_uint(f);
    return (u & 0x80000000u) ? ~u : (u | 0x80000000u);
}
__device__ __forceinline__ float funkey(unsigned k) {
    return __uint_as_float((k & 0x80000000u) ? (k & 0x7FFFFFFFu) : ~k);
}

// ---------------------------- PTX helpers -----------------------------------
__device__ __forceinline__ uint32_t smem_u32(const void* p) {
    uint32_t a;
    asm("{ .reg .u64 t; cvta.to.shared.u64 t, %1; cvt.u32.u64 %0, t; }"
        : "=r"(a) : "l"(p));
    return a;
}
__device__ __forceinline__ void cp16(uint32_t dst, const void* src) {
    asm volatile("cp.async.cg.shared.global [%0], [%1], 16;" :: "r"(dst), "l"(src));
}
#define CP_COMMIT() asm volatile("cp.async.commit_group;" ::: "memory")
#define CP_WAIT1()  asm volatile("cp.async.wait_group 1;"  ::: "memory")

__device__ __forceinline__ void ldsm4(uint32_t& r0, uint32_t& r1, uint32_t& r2, uint32_t& r3,
                                      uint32_t addr) {
    asm volatile("ldmatrix.sync.aligned.m8n8.x4.shared.b16 {%0,%1,%2,%3}, [%4];"
                 : "=r"(r0), "=r"(r1), "=r"(r2), "=r"(r3) : "r"(addr));
}
__device__ __forceinline__ void mma16816(float* d, const uint32_t* a, const uint32_t* b) {
    asm volatile(
        "mma.sync.aligned.m16n8k16.row.col.f32.f16.f16.f32 "
        "{%0,%1,%2,%3}, {%4,%5,%6,%7}, {%8,%9}, {%0,%1,%2,%3};"
        : "+f"(d[0]), "+f"(d[1]), "+f"(d[2]), "+f"(d[3])
        : "r"(a[0]), "r"(a[1]), "r"(a[2]), "r"(a[3]), "r"(b[0]), "r"(b[1]));
}
__device__ __forceinline__ uint32_t h2u(__half2 h) {
    uint32_t u;
    memcpy(&u, &h, 4);
    return u;
}

// ------------------------------- init ---------------------------------------
__global__ void init_kernel() {
    int t = blockIdx.x * blockDim.x + threadIdx.x;
    int n = gridDim.x * blockDim.x;
    for (int i = t; i < BATCH; i += n) g_rowmin[i] = INF_KEY;
    for (int i = t; i < NSUB;  i += n) g_colmin[i] = INF_KEY;
    for (int i = t; i < NSUP;  i += n) g_ssrow[i]  = INF_KEY;
    for (int i = t; i < NSUB;  i += n) g_sscol[i]  = INF_KEY;
    // zero pad rows [1224,1280) and [1480,1536)
    for (int i = t; i < 56 * LATENT; i += n) {
        int r = i / LATENT, k = i % LATENT;
        g_Bh[(size_t)(M2BASE + NOUT + r) * LATENT + k] = __float2half(0.f);
        g_Bh[(size_t)(M1BASE + NOUT + r) * LATENT + k] = __float2half(0.f);
    }
}

// -------------- fused row-norm + fp32->fp16 convert (warp per row) -----------
__global__ void prep_convert(const float* __restrict__ X, __half* __restrict__ dst,
                             float* __restrict__ nrm, int rows) {
    int w    = (blockIdx.x * blockDim.x + threadIdx.x) >> 5;
    int lane = threadIdx.x & 31;
    if (w >= rows) return;
    const float4* p = (const float4*)(X + (size_t)w * LATENT);
    __half* drow = dst + (size_t)w * LATENT;
    float s = 0.f;
#pragma unroll
    for (int i = 0; i < 4; i++) {
        float4 v = p[lane + 32 * i];
        s += v.x * v.x + v.y * v.y + v.z * v.z + v.w * v.w;
        uint2 u;
        u.x = h2u(__floats2half2_rn(v.x, v.y));
        u.y = h2u(__floats2half2_rn(v.z, v.w));
        *(uint2*)(drow + (lane + 32 * i) * 4) = u;
    }
#pragma unroll
    for (int o = 16; o; o >>= 1) s += __shfl_xor_sync(0xFFFFFFFFu, s, o);
    if (!lane) nrm[w] = s;
}

// ------------------------------ sup norms ------------------------------------
__global__ void norms_sup_kernel(const float* __restrict__ X) {
    int w    = (blockIdx.x * blockDim.x + threadIdx.x) >> 5;
    int lane = threadIdx.x & 31;
    if (w >= NSUP) return;
    const float4* p = (const float4*)(X + (size_t)w * LATENT);
    float s = 0.f;
#pragma unroll
    for (int i = 0; i < 4; i++) {
        float4 v = p[lane + 32 * i];
        s += v.x * v.x + v.y * v.y + v.z * v.z + v.w * v.w;
    }
#pragma unroll
    for (int o = 16; o; o >>= 1) s += __shfl_xor_sync(0xFFFFFFFFu, s, o);
    if (!lane) g_yysup[w] = s;
}

// ---------------- M build:  g_Bh[rowbase+o][k] = sum_j W[o][j] * P[j][k] ------
__global__ void buildM_kernel(const float* __restrict__ P, const float* __restrict__ W,
                              int J, int rowbase) {
    __shared__ float sP[64][17];   // [j][k]
    __shared__ float sW[16][65];   // [o][j]
    int k0 = blockIdx.x * 16, o0 = blockIdx.y * 16;
    int tx = threadIdx.x, ty = threadIdx.y;
    int tid = ty * 16 + tx;
    float acc = 0.f;
    for (int j0 = 0; j0 < J; j0 += 64) {
        for (int i = tid; i < 64 * 16; i += 256) {
            int jj = i / 16, kk = i % 16;
            sP[jj][kk] = P[(size_t)(j0 + jj) * LATENT + k0 + kk];
        }
        for (int i = tid; i < 16 * 64; i += 256) {
            int oo = i / 64, jj = i % 64;
            int o = o0 + oo;
            sW[oo][jj] = (o < NOUT) ? W[(size_t)o * J + j0 + jj] : 0.f;
        }
        __syncthreads();
#pragma unroll 16
        for (int jj = 0; jj < 64; jj++) acc += sP[jj][tx] * sW[ty][jj];
        __syncthreads();
    }
    if (o0 + ty < NOUT)
        g_Bh[(size_t)(rowbase + o0 + ty) * LATENT + k0 + tx] = __float2half_rn(acc);
}

// ------------- s/c vectors ----------------------------------------------------
__global__ void svec_kernel(const float* __restrict__ W1, const float* __restrict__ b1,
                            const float* __restrict__ W2, const float* __restrict__ b2) {
    int w = (blockIdx.x * blockDim.x + threadIdx.x) >> 5;
    int lane = threadIdx.x & 31;
    if (w >= 2 * NOUT) return;
    const float *W, *b, *yy;
    float *s, *c;
    int J, o;
    if (w < NOUT) { o = w;        W = W1; b = b1; yy = g_yysup; s = g_s1; c = g_c1; J = NSUP; }
    else          { o = w - NOUT; W = W2; b = b2; yy = g_yysub; s = g_s2; c = g_c2; J = NSUB; }
    float sw = 0.f, cy = 0.f;
    for (int j = lane; j < J; j += 32) {
        float wv = W[(size_t)o * J + j];
        sw += wv;
        cy += yy[j] * wv;
    }
#pragma unroll
    for (int off = 16; off; off >>= 1) {
        sw += __shfl_xor_sync(0xFFFFFFFFu, sw, off);
        cy += __shfl_xor_sync(0xFFFFFFFFu, cy, off);
    }
    if (!lane) { s[o] = sw; c[o] = b[o] + cy; }
}

// ------------------- super-sub distances: r3/r4 min sources -------------------
// grid (32, 4): x = 8 sup rows, y = 256-wide sub slice; one j per thread.
__global__ void supersub_kernel(const float* __restrict__ sup, const float* __restrict__ sub) {
    __shared__ float4 sp[8][LATENT / 4];
    __shared__ float  red[256];
    int i0 = blockIdx.x * 8, tid = threadIdx.x;
    int j = blockIdx.y * 256 + tid;
    for (int t = tid; t < 8 * (LATENT / 4); t += 256) {
        int r = t / (LATENT / 4), k = t % (LATENT / 4);
        sp[r][k] = ((const float4*)(sup + (size_t)(i0 + r) * LATENT))[k];
    }
    __syncthreads();

    const float4* pj = (const float4*)(sub + (size_t)j * LATENT);
    float dot[8];
#pragma unroll
    for (int r = 0; r < 8; r++) dot[r] = 0.f;
    for (int k = 0; k < LATENT / 4; k++) {
        float4 p = pj[k];
#pragma unroll
        for (int r = 0; r < 8; r++) {
            float4 a = sp[r][k];
            dot[r] += a.x * p.x + a.y * p.y + a.z * p.z + a.w * p.w;
        }
    }
    float yj = g_yysub[j], cmin = 3.4e38f;
    float dr[8];
#pragma unroll
    for (int r = 0; r < 8; r++) {
        dr[r] = g_yysup[i0 + r] - 2.f * dot[r] + yj;
        cmin = fminf(cmin, dr[r]);
    }
    atomicMin(&g_sscol[j], fkey(cmin));
#pragma unroll
    for (int r = 0; r < 8; r++) {
        red[tid] = dr[r];
        __syncthreads();
        for (int s = 128; s; s >>= 1) {
            if (tid < s) red[tid] = fminf(red[tid], red[tid + s]);
            __syncthreads();
        }
        if (tid == 0) atomicMin(&g_ssrow[i0 + r], fkey(red[0]));
        __syncthreads();
    }
}

// ------------------------------- main GEMM (mma.sync fp16) -------------------
// grid (6, 256). 512 threads = 16 warps: wm = wid&3 (rows 32), wn = wid>>2 (cols 64).
// Warp tile 32x64. KC=64, 3 stages, ONE barrier per k-iter.
__device__ __forceinline__ void load_chunk(uint32_t astage, const __half* Abase,
                                           const __half* Bbase, int k0, int tid) {
#pragma unroll
    for (int t = 0; t < 2; t++) {            // A: 128 rows x 8 x 16B = 1024 segs
        int seg = tid + t * NTHREADS;
        int row = seg >> 3, q = seg & 7;
        cp16(astage + row * (ROWSTR_H * 2) + q * 16,
             Abase + (size_t)row * LATENT + k0 + q * 8);
    }
    uint32_t bstage = astage + ABYTES;
#pragma unroll
    for (int t = 0; t < 4; t++) {            // B: 256 rows x 8 x 16B = 2048 segs
        int seg = tid + t * NTHREADS;
        int row = seg >> 3, q = seg & 7;
        cp16(bstage + row * (ROWSTR_H * 2) + q * 16,
             Bbase + (size_t)row * LATENT + k0 + q * 8);
    }
}

__global__ __launch_bounds__(NTHREADS) void gemm_tc(
    float* __restrict__ outSub, float* __restrict__ outSup)
{
    extern __shared__ char dyn[];
    __shared__ unsigned s_row[MTILE], s_col[NTILE];
    __shared__ float sh_c0[NTILE], sh_c1[NTILE];

    const int tid = threadIdx.x;
    const int wid = tid >> 5, lane = tid & 31;
    const int grp = lane >> 2, tig = lane & 3;
    const int wm = wid & 3, wn = wid >> 2;
    const int bn = blockIdx.x, bm = blockIdx.y;
    const uint32_t dynb = smem_u32(dyn);

    if (tid < MTILE) s_row[tid] = INF_KEY;
    if (tid < NTILE) {
        s_col[tid] = INF_KEY;
        if (bn < 4) {
            sh_c0[tid] = g_yysub[bn * NTILE + tid];
        } else {
            const float* sv = (bn == 4) ? g_s2 : g_s1;
            const float* cv = (bn == 4) ? g_c2 : g_c1;
            sh_c0[tid] = (tid < NOUT) ? sv[tid] : 0.f;
            sh_c1[tid] = (tid < NOUT) ? cv[tid] : 0.f;
        }
    }

    const __half* Abase = g_Ah + (size_t)bm * MTILE * LATENT;
    const __half* Bbase = g_Bh + (size_t)bn * NTILE * LATENT;

    // prologue: stages 0,1
#pragma unroll
    for (int s = 0; s < NSTAGES - 1; s++) {
        load_chunk(dynb + s * STAGE_BYTES, Abase, Bbase, s * KC, tid);
        CP_COMMIT();
    }

    float acc[2][8][4];
#pragma unroll
    for (int mf = 0; mf < 2; mf++)
#pragma unroll
        for (int nf = 0; nf < 8; nf++)
#pragma unroll
            for (int e = 0; e < 4; e++) acc[mf][nf][e] = 0.f;

    // ldmatrix lane address offsets (in halves)
    const int a_moff = ((lane >> 3) & 1) * 8 + (lane & 7);
    const int a_koff = (lane >> 4) * 8;
    const int b_noff = (lane >> 4) * 8 + (lane & 7);
    const int b_koff = ((lane >> 3) & 1) * 8;

    int stage = 0;
    for (int k = 0; k < KITERS; k++) {
        CP_WAIT1();
        __syncthreads();
        // prefetch into the stage freed at iter k-1 (barrier above guarantees safety)
        if (k + NSTAGES - 1 < KITERS) {
            int ps = stage + 2;
            if (ps >= NSTAGES) ps -= NSTAGES;
            load_chunk(dynb + ps * STAGE_BYTES, Abase, Bbase, (k + NSTAGES - 1) * KC, tid);
        }
        CP_COMMIT();

        const uint32_t As = dynb + stage * STAGE_BYTES;
        const uint32_t Bs = As + ABYTES;
#pragma unroll
        for (int ks = 0; ks < 4; ks++) {
            const int kb = ks * 16;
            uint32_t a[2][4], b[8][2];
            {
                uint32_t addr = As + (uint32_t)(((wm * 32 + a_moff) * ROWSTR_H
                                                 + kb + a_koff) * 2);
                ldsm4(a[0][0], a[0][1], a[0][2], a[0][3], addr);
                addr = As + (uint32_t)(((wm * 32 + 16 + a_moff) * ROWSTR_H
                                         + kb + a_koff) * 2);
                ldsm4(a[1][0], a[1][1], a[1][2], a[1][3], addr);
            }
#pragma unroll
            for (int nfp = 0; nfp < 4; nfp++) {
                uint32_t addr = Bs + (uint32_t)(((wn * 64 + nfp * 16 + b_noff) * ROWSTR_H
                                                 + kb + b_koff) * 2);
                ldsm4(b[2 * nfp][0], b[2 * nfp][1], b[2 * nfp + 1][0], b[2 * nfp + 1][1], addr);
            }
#pragma unroll
            for (int mf = 0; mf < 2; mf++)
#pragma unroll
                for (int nf = 0; nf < 8; nf++)
                    mma16816(acc[mf][nf], a[mf], b[nf]);
        }
        if (++stage == NSTAGES) stage = 0;
    }

    // ------------------------------ epilogue ---------------------------------
    float xr[2][2];
#pragma unroll
    for (int mf = 0; mf < 2; mf++)
#pragma unroll
        for (int h = 0; h < 2; h++)
            xr[mf][h] = g_xx[bm * MTILE + wm * 32 + mf * 16 + h * 8 + grp];

    if (bn < 4) {                                      // distance region
#pragma unroll
        for (int mf = 0; mf < 2; mf++)
#pragma unroll
            for (int nf = 0; nf < 8; nf++) {
                float y0 = sh_c0[wn * 64 + nf * 8 + tig * 2];
                float y1 = sh_c0[wn * 64 + nf * 8 + tig * 2 + 1];
                acc[mf][nf][0] = xr[mf][0] - 2.f * acc[mf][nf][0] + y0;
                acc[mf][nf][1] = xr[mf][0] - 2.f * acc[mf][nf][1] + y1;
                acc[mf][nf][2] = xr[mf][1] - 2.f * acc[mf][nf][2] + y0;
                acc[mf][nf][3] = xr[mf][1] - 2.f * acc[mf][nf][3] + y1;
            }
        // row mins
#pragma unroll
        for (int mf = 0; mf < 2; mf++)
#pragma unroll
            for (int h = 0; h < 2; h++) {
                float m = 3.4e38f;
#pragma unroll
                for (int nf = 0; nf < 8; nf++)
                    m = fminf(m, fminf(acc[mf][nf][h * 2], acc[mf][nf][h * 2 + 1]));
                m = fminf(m, __shfl_xor_sync(0xFFFFFFFFu, m, 1));
                m = fminf(m, __shfl_xor_sync(0xFFFFFFFFu, m, 2));
                if (tig == 0)
                    atomicMin(&s_row[wm * 32 + mf * 16 + h * 8 + grp], fkey(m));
            }
        // col mins
#pragma unroll
        for (int nf = 0; nf < 8; nf++)
#pragma unroll
            for (int c = 0; c < 2; c++) {
                float m = 3.4e38f;
#pragma unroll
                for (int mf = 0; mf < 2; mf++)
                    m = fminf(m, fminf(acc[mf][nf][c], acc[mf][nf][2 + c]));
                m = fminf(m, __shfl_xor_sync(0xFFFFFFFFu, m, 4));
                m = fminf(m, __shfl_xor_sync(0xFFFFFFFFu, m, 8));
                m = fminf(m, __shfl_xor_sync(0xFFFFFFFFu, m, 16));
                if (grp == 0)
                    atomicMin(&s_col[wn * 64 + nf * 8 + tig * 2 + c], fkey(m));
            }
        __syncthreads();
        if (tid < MTILE) atomicMin(&g_rowmin[bm * MTILE + tid], s_row[tid]);
        if (tid < NTILE) atomicMin(&g_colmin[bn * NTILE + tid], s_col[tid]);
    } else {                                           // linear output regions
        float* outp = (bn == 4) ? outSub : outSup;
#pragma unroll
        for (int mf = 0; mf < 2; mf++)
#pragma unroll
            for (int h = 0; h < 2; h++) {
                int row = bm * MTILE + wm * 32 + mf * 16 + h * 8 + grp;
                float xv = xr[mf][h];
#pragma unroll
                for (int nf = 0; nf < 8; nf++) {
                    int o = wn * 64 + nf * 8 + tig * 2;
                    if (o < NOUT) {
                        float2 v;
                        v.x = xv * sh_c0[o]     - 2.f * acc[mf][nf][h * 2]     + sh_c1[o];
                        v.y = xv * sh_c0[o + 1] - 2.f * acc[mf][nf][h * 2 + 1] + sh_c1[o + 1];
                        *(float2*)(outp + (size_t)row * NOUT + o) = v;
                    }
                }
            }
    }
}

// ------------------------------- finalize ------------------------------------
__global__ void finalize_kernel(float* __restrict__ out4) {
    __shared__ float red[1024];
    int tid = threadIdx.x;
    float r1 = 0.f, r2 = 0.f, r3 = 0.f;

    red[tid] = funkey(g_colmin[tid]);
    __syncthreads();
    for (int s = 512; s > 0; s >>= 1) { if (tid < s) red[tid] += red[tid + s]; __syncthreads(); }
    if (tid == 0) r1 = red[0] * (1.f / NSUB);
    __syncthreads();

    float acc = 0.f;
    for (int i = tid; i < BATCH; i += 1024) acc += funkey(g_rowmin[i]);
    red[tid] = acc;
    __syncthreads();
    for (int s = 512; s > 0; s >>= 1) { if (tid < s) red[tid] += red[tid + s]; __syncthreads(); }
    if (tid == 0) r2 = red[0] * (1.f / BATCH);
    __syncthreads();

    red[tid] = (tid < NSUP) ? funkey(g_ssrow[tid]) : 0.f;
    __syncthreads();
    for (int s = 512; s > 0; s >>= 1) { if (tid < s) red[tid] += red[tid + s]; __syncthreads(); }
    if (tid == 0) r3 = red[0] * (1.f / NSUP);
    __syncthreads();

    red[tid] = funkey(g_sscol[tid]);
    __syncthreads();
    for (int s = 512; s > 0; s >>= 1) { if (tid < s) red[tid] += red[tid + s]; __syncthreads(); }
    if (tid == 0) {
        out4[0] = r1; out4[1] = r2; out4[2] = r3;
        out4[3] = red[0] * (1.f / NSUB);
    }
}

// ------------------------------- launcher ------------------------------------
extern "C" void kernel_launch(void* const* d_in, const int* in_sizes, int n_in,
                              void* d_out, int out_size) {
    const float* x   = (const float*)d_in[0];
    const float* sup = (const float*)d_in[1];
    const float* sub = (const float*)d_in[2];
    const float* W1  = (const float*)d_in[3];
    const float* b1  = (const float*)d_in[4];
    const float* W2  = (const float*)d_in[5];
    const float* b2  = (const float*)d_in[6];
    float* out    = (float*)d_out;
    float* outSub = out;
    float* outSup = out + (size_t)BATCH * NOUT;
    float* out4   = out + (size_t)2 * BATCH * NOUT;

    cudaFuncSetAttribute(gemm_tc, cudaFuncAttributeMaxDynamicSharedMemorySize, SMEM_DYN);

    __half *dAh = nullptr, *dBh = nullptr;
    float *dxx = nullptr, *dyysub = nullptr;
    cudaGetSymbolAddress((void**)&dAh, g_Ah);
    cudaGetSymbolAddress((void**)&dBh, g_Bh);
    cudaGetSymbolAddress((void**)&dxx, g_xx);
    cudaGetSymbolAddress((void**)&dyysub, g_yysub);

    init_kernel<<<128, 256>>>();

    prep_convert<<<(BATCH * 32 + 255) / 256, 256>>>(x,   dAh, dxx,    BATCH);
    prep_convert<<<(NSUB  * 32 + 255) / 256, 256>>>(sub, dBh, dyysub, NSUB);
    norms_sup_kernel<<<(NSUP * 32 + 255) / 256, 256>>>(sup);

    buildM_kernel<<<dim3(LATENT / 16, (NOUT + 15) / 16), dim3(16, 16)>>>(sub, W2, NSUB, M2BASE);
    buildM_kernel<<<dim3(LATENT / 16, (NOUT + 15) / 16), dim3(16, 16)>>>(sup, W1, NSUP, M1BASE);

    svec_kernel<<<(2 * NOUT * 32 + 255) / 256, 256>>>(W1, b1, W2, b2);
    supersub_kernel<<<dim3(NSUP / 8, 4), 256>>>(sup, sub);

    gemm_tc<<<dim3(BROWS / NTILE, BATCH / MTILE), NTHREADS, SMEM_DYN>>>(outSub, outSup);

    finalize_kernel<<<1, 1024>>>(out4);
}

// round 10
// speedup vs baseline: 1.3244x; 1.0985x over previous
#include <cuda_runtime.h>
#include <cuda_fp16.h>
#include <cstdint>
#include <cstddef>
#include <cstring>

// ---------------------------------------------------------------------------
#define BATCH   32768
#define LATENT  512
#define NSUP    256
#define NSUB    1024
#define NOUT    200
#define BROWS   1536              // fused B rows: [sub | M2(pad to 256) | M1(pad to 256)]
#define M2BASE  1024
#define M1BASE  1280
#define INF_KEY 0xFFFFFFFFu

// main GEMM tiling (fp16 operands, fp32 accum)
#define MTILE    128
#define NTILE    256
#define NTHREADS 512
#define KC       64                        // k-chunk in halves (128B payload per row)
#define NSTAGES  3
#define KITERS   (LATENT / KC)             // 8
#define ROWSTR_H 72                        // smem row stride in halves (144B, conflict-free)
#define ABYTES   (MTILE * ROWSTR_H * 2)    // 18432
#define BBYTES   (NTILE * ROWSTR_H * 2)    // 36864
#define STAGE_BYTES (ABYTES + BBYTES)      // 55296
#define SMEM_DYN (NSTAGES * STAGE_BYTES)   // 165888

// ---------------------------- device scratch --------------------------------
__device__ __half   g_Ah[BATCH * LATENT];    // x in fp16
__device__ __half   g_Bh[BROWS * LATENT];    // fused B in fp16, [N][K] row-major
__device__ float    g_xx[BATCH];
__device__ float    g_yysub[NSUB];
__device__ float    g_yysup[NSUP];
__device__ float    g_s1[NOUT], g_c1[NOUT], g_s2[NOUT], g_c2[NOUT];
__device__ unsigned g_rowmin[BATCH];
__device__ unsigned g_colmin[NSUB];
__device__ unsigned g_ssrow[NSUP];
__device__ unsigned g_sscol[NSUB];

// order-preserving float <-> uint keys
__device__ __forceinline__ unsigned fkey(float f) {
    unsigned u = __float_as_uint(f);
    return (u & 0x80000000u) ? ~u : (u | 0x80000000u);
}
__device__ __forceinline__ float funkey(unsigned k) {
    return __uint_as_float((k & 0x80000000u) ? (k & 0x7FFFFFFFu) : ~k);
}

// ---------------------------- PTX helpers -----------------------------------
__device__ __forceinline__ uint32_t smem_u32(const void* p) {
    uint32_t a;
    asm("{ .reg .u64 t; cvta.to.shared.u64 t, %1; cvt.u32.u64 %0, t; }"
        : "=r"(a) : "l"(p));
    return a;
}
__device__ __forceinline__ void cp16(uint32_t dst, const void* src) {
    asm volatile("cp.async.cg.shared.global [%0], [%1], 16;" :: "r"(dst), "l"(src));
}
#define CP_COMMIT() asm volatile("cp.async.commit_group;" ::: "memory")
#define CP_WAIT1()  asm volatile("cp.async.wait_group 1;"  ::: "memory")

__device__ __forceinline__ void ldsm4(uint32_t& r0, uint32_t& r1, uint32_t& r2, uint32_t& r3,
                                      uint32_t addr) {
    asm volatile("ldmatrix.sync.aligned.m8n8.x4.shared.b16 {%0,%1,%2,%3}, [%4];"
                 : "=r"(r0), "=r"(r1), "=r"(r2), "=r"(r3) : "r"(addr));
}
__device__ __forceinline__ void mma16816(float* d, const uint32_t* a, const uint32_t* b) {
    asm volatile(
        "mma.sync.aligned.m16n8k16.row.col.f32.f16.f16.f32 "
        "{%0,%1,%2,%3}, {%4,%5,%6,%7}, {%8,%9}, {%0,%1,%2,%3};"
        : "+f"(d[0]), "+f"(d[1]), "+f"(d[2]), "+f"(d[3])
        : "r"(a[0]), "r"(a[1]), "r"(a[2]), "r"(a[3]), "r"(b[0]), "r"(b[1]));
}
__device__ __forceinline__ uint32_t h2u(__half2 h) {
    uint32_t u;
    memcpy(&u, &h, 4);
    return u;
}

// ------------------------- fused prep kernel ---------------------------------
// grid 4384 x 256:
//   [0,4096)    : x  convert+norm   (8 rows/block, warp per row)
//   [4096,4224) : sub convert+norm
//   [4224,4256) : sup norms
//   [4256,4384) : init of min arrays + g_Bh pad rows
__device__ __forceinline__ void conv_row(const float* __restrict__ X,
                                         __half* __restrict__ dst,
                                         float* __restrict__ nrm, int w, int lane) {
    const float4* p = (const float4*)(X + (size_t)w * LATENT);
    __half* drow = dst + (size_t)w * LATENT;
    float s = 0.f;
#pragma unroll
    for (int i = 0; i < 4; i++) {
        float4 v = p[lane + 32 * i];
        s += v.x * v.x + v.y * v.y + v.z * v.z + v.w * v.w;
        uint2 u;
        u.x = h2u(__floats2half2_rn(v.x, v.y));
        u.y = h2u(__floats2half2_rn(v.z, v.w));
        *(uint2*)(drow + (lane + 32 * i) * 4) = u;
    }
#pragma unroll
    for (int o = 16; o; o >>= 1) s += __shfl_xor_sync(0xFFFFFFFFu, s, o);
    if (!lane) nrm[w] = s;
}

__global__ void prep_all(const float* __restrict__ x, const float* __restrict__ sub,
                         const float* __restrict__ sup) {
    int b = blockIdx.x, tid = threadIdx.x;
    int wv = tid >> 5, lane = tid & 31;
    if (b < 4096) {
        conv_row(x, g_Ah, g_xx, b * 8 + wv, lane);
    } else if (b < 4224) {
        conv_row(sub, g_Bh, g_yysub, (b - 4096) * 8 + wv, lane);
    } else if (b < 4256) {
        int w = (b - 4224) * 8 + wv;
        const float4* p = (const float4*)(sup + (size_t)w * LATENT);
        float s = 0.f;
#pragma unroll
        for (int i = 0; i < 4; i++) {
            float4 v = p[lane + 32 * i];
            s += v.x * v.x + v.y * v.y + v.z * v.z + v.w * v.w;
        }
#pragma unroll
        for (int o = 16; o; o >>= 1) s += __shfl_xor_sync(0xFFFFFFFFu, s, o);
        if (!lane) g_yysup[w] = s;
    } else {
        int t = (b - 4256) * 256 + tid;            // 32768 threads
        g_rowmin[t] = INF_KEY;
        if (t < NSUB)  { g_colmin[t] = INF_KEY; g_sscol[t] = INF_KEY; }
        if (t < NSUP)  g_ssrow[t] = INF_KEY;
        if (t < 56 * LATENT) {
            int r = t / LATENT, k = t % LATENT;
            g_Bh[(size_t)(M2BASE + NOUT + r) * LATENT + k] = __float2half(0.f);
            g_Bh[(size_t)(M1BASE + NOUT + r) * LATENT + k] = __float2half(0.f);
        }
    }
}

// ------------------------- fused mid kernel ----------------------------------
// grid 1010 x 256:
//   [0,416)    : buildM2 (sub, W2)    32 x 13 tiles
//   [416,832)  : buildM1 (sup, W1)
//   [832,882)  : svec (8 warps/block, 400 warps)
//   [882,1010) : supersub (32 x 4)
__device__ void buildM_body(const float* __restrict__ P, const float* __restrict__ W,
                            int J, int rowbase, int bb) {
    __shared__ float sP[64][17];
    __shared__ float sW[16][65];
    int k0 = (bb & 31) * 16, o0 = (bb >> 5) * 16;
    int tid = threadIdx.x;
    int tx = tid & 15, ty = tid >> 4;
    float acc = 0.f;
    for (int j0 = 0; j0 < J; j0 += 64) {
        for (int i = tid; i < 64 * 16; i += 256) {
            int jj = i / 16, kk = i % 16;
            sP[jj][kk] = P[(size_t)(j0 + jj) * LATENT + k0 + kk];
        }
        for (int i = tid; i < 16 * 64; i += 256) {
            int oo = i / 64, jj = i % 64;
            int o = o0 + oo;
            sW[oo][jj] = (o < NOUT) ? W[(size_t)o * J + j0 + jj] : 0.f;
        }
        __syncthreads();
#pragma unroll 16
        for (int jj = 0; jj < 64; jj++) acc += sP[jj][tx] * sW[ty][jj];
        __syncthreads();
    }
    if (o0 + ty < NOUT)
        g_Bh[(size_t)(rowbase + o0 + ty) * LATENT + k0 + tx] = __float2half_rn(acc);
}

__device__ void svec_body(const float* __restrict__ W1, const float* __restrict__ b1,
                          const float* __restrict__ W2, const float* __restrict__ b2,
                          int bb) {
    int w = bb * 8 + (threadIdx.x >> 5);
    int lane = threadIdx.x & 31;
    if (w >= 2 * NOUT) return;
    const float *W, *b, *yy;
    float *s, *c;
    int J, o;
    if (w < NOUT) { o = w;        W = W1; b = b1; yy = g_yysup; s = g_s1; c = g_c1; J = NSUP; }
    else          { o = w - NOUT; W = W2; b = b2; yy = g_yysub; s = g_s2; c = g_c2; J = NSUB; }
    float sw = 0.f, cy = 0.f;
    for (int j = lane; j < J; j += 32) {
        float wv = W[(size_t)o * J + j];
        sw += wv;
        cy += yy[j] * wv;
    }
#pragma unroll
    for (int off = 16; off; off >>= 1) {
        sw += __shfl_xor_sync(0xFFFFFFFFu, sw, off);
        cy += __shfl_xor_sync(0xFFFFFFFFu, cy, off);
    }
    if (!lane) { s[o] = sw; c[o] = b[o] + cy; }
}

__device__ void supersub_body(const float* __restrict__ sup, const float* __restrict__ sub,
                              int bb) {
    __shared__ float4 sp[8][LATENT / 4];
    __shared__ float  red[256];
    int i0 = (bb & 31) * 8, tid = threadIdx.x;
    int j = (bb >> 5) * 256 + tid;
    for (int t = tid; t < 8 * (LATENT / 4); t += 256) {
        int r = t / (LATENT / 4), k = t % (LATENT / 4);
        sp[r][k] = ((const float4*)(sup + (size_t)(i0 + r) * LATENT))[k];
    }
    __syncthreads();

    const float4* pj = (const float4*)(sub + (size_t)j * LATENT);
    float dot[8];
#pragma unroll
    for (int r = 0; r < 8; r++) dot[r] = 0.f;
    for (int k = 0; k < LATENT / 4; k++) {
        float4 p = pj[k];
#pragma unroll
        for (int r = 0; r < 8; r++) {
            float4 a = sp[r][k];
            dot[r] += a.x * p.x + a.y * p.y + a.z * p.z + a.w * p.w;
        }
    }
    float yj = g_yysub[j], cmin = 3.4e38f;
    float dr[8];
#pragma unroll
    for (int r = 0; r < 8; r++) {
        dr[r] = g_yysup[i0 + r] - 2.f * dot[r] + yj;
        cmin = fminf(cmin, dr[r]);
    }
    atomicMin(&g_sscol[j], fkey(cmin));
#pragma unroll
    for (int r = 0; r < 8; r++) {
        red[tid] = dr[r];
        __syncthreads();
        for (int s = 128; s; s >>= 1) {
            if (tid < s) red[tid] = fminf(red[tid], red[tid + s]);
            __syncthreads();
        }
        if (tid == 0) atomicMin(&g_ssrow[i0 + r], fkey(red[0]));
        __syncthreads();
    }
}

__global__ void mid_all(const float* __restrict__ sub, const float* __restrict__ sup,
                        const float* __restrict__ W1, const float* __restrict__ b1,
                        const float* __restrict__ W2, const float* __restrict__ b2) {
    int b = blockIdx.x;
    if (b < 416)       buildM_body(sub, W2, NSUB, M2BASE, b);
    else if (b < 832)  buildM_body(sup, W1, NSUP, M1BASE, b - 416);
    else if (b < 882)  svec_body(W1, b1, W2, b2, b - 832);
    else               supersub_body(sup, sub, b - 882);
}

// ------------------------------- main GEMM (mma.sync fp16) -------------------
// grid (6, 256). 512 threads = 16 warps: wm = wid&3 (rows 32), wn = wid>>2 (cols 64).
// Warp tile 32x64. KC=64, 3 stages, ONE barrier per k-iter.
__device__ __forceinline__ void load_chunk(uint32_t astage, const __half* Abase,
                                           const __half* Bbase, int k0, int tid) {
#pragma unroll
    for (int t = 0; t < 2; t++) {            // A: 128 rows x 8 x 16B = 1024 segs
        int seg = tid + t * NTHREADS;
        int row = seg >> 3, q = seg & 7;
        cp16(astage + row * (ROWSTR_H * 2) + q * 16,
             Abase + (size_t)row * LATENT + k0 + q * 8);
    }
    uint32_t bstage = astage + ABYTES;
#pragma unroll
    for (int t = 0; t < 4; t++) {            // B: 256 rows x 8 x 16B = 2048 segs
        int seg = tid + t * NTHREADS;
        int row = seg >> 3, q = seg & 7;
        cp16(bstage + row * (ROWSTR_H * 2) + q * 16,
             Bbase + (size_t)row * LATENT + k0 + q * 8);
    }
}

__global__ __launch_bounds__(NTHREADS) void gemm_tc(
    float* __restrict__ outSub, float* __restrict__ outSup)
{
    extern __shared__ char dyn[];
    __shared__ unsigned s_row[MTILE], s_col[NTILE];
    __shared__ float sh_c0[NTILE], sh_c1[NTILE];

    const int tid = threadIdx.x;
    const int wid = tid >> 5, lane = tid & 31;
    const int grp = lane >> 2, tig = lane & 3;
    const int wm = wid & 3, wn = wid >> 2;
    const int bn = blockIdx.x, bm = blockIdx.y;
    const uint32_t dynb = smem_u32(dyn);

    if (tid < MTILE) s_row[tid] = INF_KEY;
    if (tid < NTILE) {
        s_col[tid] = INF_KEY;
        if (bn < 4) {
            sh_c0[tid] = g_yysub[bn * NTILE + tid];
        } else {
            const float* sv = (bn == 4) ? g_s2 : g_s1;
            const float* cv = (bn == 4) ? g_c2 : g_c1;
            sh_c0[tid] = (tid < NOUT) ? sv[tid] : 0.f;
            sh_c1[tid] = (tid < NOUT) ? cv[tid] : 0.f;
        }
    }

    const __half* Abase = g_Ah + (size_t)bm * MTILE * LATENT;
    const __half* Bbase = g_Bh + (size_t)bn * NTILE * LATENT;

    // prologue: stages 0,1
#pragma unroll
    for (int s = 0; s < NSTAGES - 1; s++) {
        load_chunk(dynb + s * STAGE_BYTES, Abase, Bbase, s * KC, tid);
        CP_COMMIT();
    }

    float acc[2][8][4];
#pragma unroll
    for (int mf = 0; mf < 2; mf++)
#pragma unroll
        for (int nf = 0; nf < 8; nf++)
#pragma unroll
            for (int e = 0; e < 4; e++) acc[mf][nf][e] = 0.f;

    // ldmatrix lane address offsets (in halves)
    const int a_moff = ((lane >> 3) & 1) * 8 + (lane & 7);
    const int a_koff = (lane >> 4) * 8;
    const int b_noff = (lane >> 4) * 8 + (lane & 7);
    const int b_koff = ((lane >> 3) & 1) * 8;

    int stage = 0;
    for (int k = 0; k < KITERS; k++) {
        CP_WAIT1();
        __syncthreads();
        // prefetch into the stage freed at iter k-1 (barrier above guarantees safety)
        if (k + NSTAGES - 1 < KITERS) {
            int ps = stage + 2;
            if (ps >= NSTAGES) ps -= NSTAGES;
            load_chunk(dynb + ps * STAGE_BYTES, Abase, Bbase, (k + NSTAGES - 1) * KC, tid);
        }
        CP_COMMIT();

        const uint32_t As = dynb + stage * STAGE_BYTES;
        const uint32_t Bs = As + ABYTES;
#pragma unroll
        for (int ks = 0; ks < 4; ks++) {
            const int kb = ks * 16;
            uint32_t a[2][4], b[8][2];
            {
                uint32_t addr = As + (uint32_t)(((wm * 32 + a_moff) * ROWSTR_H
                                                 + kb + a_koff) * 2);
                ldsm4(a[0][0], a[0][1], a[0][2], a[0][3], addr);
                addr = As + (uint32_t)(((wm * 32 + 16 + a_moff) * ROWSTR_H
                                         + kb + a_koff) * 2);
                ldsm4(a[1][0], a[1][1], a[1][2], a[1][3], addr);
            }
#pragma unroll
            for (int nfp = 0; nfp < 4; nfp++) {
                uint32_t addr = Bs + (uint32_t)(((wn * 64 + nfp * 16 + b_noff) * ROWSTR_H
                                                 + kb + b_koff) * 2);
                ldsm4(b[2 * nfp][0], b[2 * nfp][1], b[2 * nfp + 1][0], b[2 * nfp + 1][1], addr);
            }
#pragma unroll
            for (int mf = 0; mf < 2; mf++)
#pragma unroll
                for (int nf = 0; nf < 8; nf++)
                    mma16816(acc[mf][nf], a[mf], b[nf]);
        }
        if (++stage == NSTAGES) stage = 0;
    }

    // ------------------------------ epilogue ---------------------------------
    float xr[2][2];
#pragma unroll
    for (int mf = 0; mf < 2; mf++)
#pragma unroll
        for (int h = 0; h < 2; h++)
            xr[mf][h] = g_xx[bm * MTILE + wm * 32 + mf * 16 + h * 8 + grp];

    if (bn < 4) {                                      // distance region
#pragma unroll
        for (int mf = 0; mf < 2; mf++)
#pragma unroll
            for (int nf = 0; nf < 8; nf++) {
                float y0 = sh_c0[wn * 64 + nf * 8 + tig * 2];
                float y1 = sh_c0[wn * 64 + nf * 8 + tig * 2 + 1];
                acc[mf][nf][0] = xr[mf][0] - 2.f * acc[mf][nf][0] + y0;
                acc[mf][nf][1] = xr[mf][0] - 2.f * acc[mf][nf][1] + y1;
                acc[mf][nf][2] = xr[mf][1] - 2.f * acc[mf][nf][2] + y0;
                acc[mf][nf][3] = xr[mf][1] - 2.f * acc[mf][nf][3] + y1;
            }
        // row mins
#pragma unroll
        for (int mf = 0; mf < 2; mf++)
#pragma unroll
            for (int h = 0; h < 2; h++) {
                float m = 3.4e38f;
#pragma unroll
                for (int nf = 0; nf < 8; nf++)
                    m = fminf(m, fminf(acc[mf][nf][h * 2], acc[mf][nf][h * 2 + 1]));
                m = fminf(m, __shfl_xor_sync(0xFFFFFFFFu, m, 1));
                m = fminf(m, __shfl_xor_sync(0xFFFFFFFFu, m, 2));
                if (tig == 0)
                    atomicMin(&s_row[wm * 32 + mf * 16 + h * 8 + grp], fkey(m));
            }
        // col mins
#pragma unroll
        for (int nf = 0; nf < 8; nf++)
#pragma unroll
            for (int c = 0; c < 2; c++) {
                float m = 3.4e38f;
#pragma unroll
                for (int mf = 0; mf < 2; mf++)
                    m = fminf(m, fminf(acc[mf][nf][c], acc[mf][nf][2 + c]));
                m = fminf(m, __shfl_xor_sync(0xFFFFFFFFu, m, 4));
                m = fminf(m, __shfl_xor_sync(0xFFFFFFFFu, m, 8));
                m = fminf(m, __shfl_xor_sync(0xFFFFFFFFu, m, 16));
                if (grp == 0)
                    atomicMin(&s_col[wn * 64 + nf * 8 + tig * 2 + c], fkey(m));
            }
        __syncthreads();
        if (tid < MTILE) atomicMin(&g_rowmin[bm * MTILE + tid], s_row[tid]);
        if (tid < NTILE) atomicMin(&g_colmin[bn * NTILE + tid], s_col[tid]);
    } else {                                           // linear output regions
        float* outp = (bn == 4) ? outSub : outSup;
#pragma unroll
        for (int mf = 0; mf < 2; mf++)
#pragma unroll
            for (int h = 0; h < 2; h++) {
                int row = bm * MTILE + wm * 32 + mf * 16 + h * 8 + grp;
                float xv = xr[mf][h];
#pragma unroll
                for (int nf = 0; nf < 8; nf++) {
                    int o = wn * 64 + nf * 8 + tig * 2;
                    if (o < NOUT) {
                        float2 v;
                        v.x = xv * sh_c0[o]     - 2.f * acc[mf][nf][h * 2]     + sh_c1[o];
                        v.y = xv * sh_c0[o + 1] - 2.f * acc[mf][nf][h * 2 + 1] + sh_c1[o + 1];
                        *(float2*)(outp + (size_t)row * NOUT + o) = v;
                    }
                }
            }
    }
}

// ------------------------------- finalize ------------------------------------
__global__ void finalize_kernel(float* __restrict__ out4) {
    __shared__ float red[1024];
    int tid = threadIdx.x;
    float r1 = 0.f, r2 = 0.f, r3 = 0.f;

    red[tid] = funkey(g_colmin[tid]);
    __syncthreads();
    for (int s = 512; s > 0; s >>= 1) { if (tid < s) red[tid] += red[tid + s]; __syncthreads(); }
    if (tid == 0) r1 = red[0] * (1.f / NSUB);
    __syncthreads();

    float acc = 0.f;
    for (int i = tid; i < BATCH; i += 1024) acc += funkey(g_rowmin[i]);
    red[tid] = acc;
    __syncthreads();
    for (int s = 512; s > 0; s >>= 1) { if (tid < s) red[tid] += red[tid + s]; __syncthreads(); }
    if (tid == 0) r2 = red[0] * (1.f / BATCH);
    __syncthreads();

    red[tid] = (tid < NSUP) ? funkey(g_ssrow[tid]) : 0.f;
    __syncthreads();
    for (int s = 512; s > 0; s >>= 1) { if (tid < s) red[tid] += red[tid + s]; __syncthreads(); }
    if (tid == 0) r3 = red[0] * (1.f / NSUP);
    __syncthreads();

    red[tid] = funkey(g_sscol[tid]);
    __syncthreads();
    for (int s = 512; s > 0; s >>= 1) { if (tid < s) red[tid] += red[tid + s]; __syncthreads(); }
    if (tid == 0) {
        out4[0] = r1; out4[1] = r2; out4[2] = r3;
        out4[3] = red[0] * (1.f / NSUB);
    }
}

// ------------------------------- launcher ------------------------------------
extern "C" void kernel_launch(void* const* d_in, const int* in_sizes, int n_in,
                              void* d_out, int out_size) {
    const float* x   = (const float*)d_in[0];
    const float* sup = (const float*)d_in[1];
    const float* sub = (const float*)d_in[2];
    const float* W1  = (const float*)d_in[3];
    const float* b1  = (const float*)d_in[4];
    const float* W2  = (const float*)d_in[5];
    const float* b2  = (const float*)d_in[6];
    float* out    = (float*)d_out;
    float* outSub = out;
    float* outSup = out + (size_t)BATCH * NOUT;
    float* out4   = out + (size_t)2 * BATCH * NOUT;

    cudaFuncSetAttribute(gemm_tc, cudaFuncAttributeMaxDynamicSharedMemorySize, SMEM_DYN);

    prep_all<<<4384, 256>>>(x, sub, sup);
    mid_all<<<1010, 256>>>(sub, sup, W1, b1, W2, b2);
    gemm_tc<<<dim3(BROWS / NTILE, BATCH / MTILE), NTHREADS, SMEM_DYN>>>(outSub, outSup);
    finalize_kernel<<<1, 1024>>>(out4);
}

// round 11
// speedup vs baseline: 1.3505x; 1.0197x over previous
#include <cuda_runtime.h>
#include <cuda_fp16.h>
#include <cstdint>
#include <cstddef>
#include <cstring>

// ---------------------------------------------------------------------------
#define BATCH   32768
#define LATENT  512
#define NSUP    256
#define NSUB    1024
#define NOUT    200
#define BROWS   1536              // fused B rows: [sub | M2(pad to 256) | M1(pad to 256)]
#define M2BASE  1024
#define M1BASE  1280
#define INF_KEY 0xFFFFFFFFu

// main GEMM tiling (fp16 operands, fp32 accum)
#define MTILE    128
#define NTILE    256
#define NTHREADS 512
#define KC       64                        // k-chunk in halves (128B payload per row)
#define NSTAGES  3
#define KITERS   (LATENT / KC)             // 8
#define ROWSTR_H 72                        // smem row stride in halves (144B, conflict-free)
#define ABYTES   (MTILE * ROWSTR_H * 2)    // 18432
#define BBYTES   (NTILE * ROWSTR_H * 2)    // 36864
#define STAGE_BYTES (ABYTES + BBYTES)      // 55296
#define SMEM_DYN (NSTAGES * STAGE_BYTES)   // 165888

// ---------------------------- device scratch --------------------------------
__device__ __half   g_Ah[BATCH * LATENT];    // x in fp16
__device__ __half   g_Bh[BROWS * LATENT];    // fused B in fp16, [N][K] row-major
__device__ float    g_xx[BATCH];
__device__ float    g_yysub[NSUB];
__device__ float    g_yysup[NSUP];
__device__ float    g_s1[NOUT], g_c1[NOUT], g_s2[NOUT], g_c2[NOUT];
__device__ unsigned g_rowmin[BATCH];
__device__ unsigned g_colmin[NSUB];
__device__ unsigned g_ssrow[NSUP];
__device__ unsigned g_sscol[NSUB];
__device__ float    g_psum[32];              // partial sums of funkey(rowmin)

// order-preserving float <-> uint keys
__device__ __forceinline__ unsigned fkey(float f) {
    unsigned u = __float_as_uint(f);
    return (u & 0x80000000u) ? ~u : (u | 0x80000000u);
}
__device__ __forceinline__ float funkey(unsigned k) {
    return __uint_as_float((k & 0x80000000u) ? (k & 0x7FFFFFFFu) : ~k);
}

// ---------------------------- PTX helpers -----------------------------------
__device__ __forceinline__ uint32_t smem_u32(const void* p) {
    uint32_t a;
    asm("{ .reg .u64 t; cvta.to.shared.u64 t, %1; cvt.u32.u64 %0, t; }"
        : "=r"(a) : "l"(p));
    return a;
}
__device__ __forceinline__ void cp16(uint32_t dst, const void* src) {
    asm volatile("cp.async.cg.shared.global [%0], [%1], 16;" :: "r"(dst), "l"(src));
}
#define CP_COMMIT() asm volatile("cp.async.commit_group;" ::: "memory")
#define CP_WAIT1()  asm volatile("cp.async.wait_group 1;"  ::: "memory")

__device__ __forceinline__ void ldsm4(uint32_t& r0, uint32_t& r1, uint32_t& r2, uint32_t& r3,
                                      uint32_t addr) {
    asm volatile("ldmatrix.sync.aligned.m8n8.x4.shared.b16 {%0,%1,%2,%3}, [%4];"
                 : "=r"(r0), "=r"(r1), "=r"(r2), "=r"(r3) : "r"(addr));
}
__device__ __forceinline__ void mma16816(float* d, const uint32_t* a, const uint32_t* b) {
    asm volatile(
        "mma.sync.aligned.m16n8k16.row.col.f32.f16.f16.f32 "
        "{%0,%1,%2,%3}, {%4,%5,%6,%7}, {%8,%9}, {%0,%1,%2,%3};"
        : "+f"(d[0]), "+f"(d[1]), "+f"(d[2]), "+f"(d[3])
        : "r"(a[0]), "r"(a[1]), "r"(a[2]), "r"(a[3]), "r"(b[0]), "r"(b[1]));
}
__device__ __forceinline__ uint32_t h2u(__half2 h) {
    uint32_t u;
    memcpy(&u, &h, 4);
    return u;
}

// ------------------------- fused prep kernel ---------------------------------
// grid 4384 x 256:
//   [0,4096)    : x  convert+norm   (8 rows/block, warp per row)
//   [4096,4224) : sub convert+norm
//   [4224,4256) : sup norms
//   [4256,4384) : init of min arrays + g_Bh pad rows
__device__ __forceinline__ void conv_row(const float* __restrict__ X,
                                         __half* __restrict__ dst,
                                         float* __restrict__ nrm, int w, int lane) {
    const float4* p = (const float4*)(X + (size_t)w * LATENT);
    __half* drow = dst + (size_t)w * LATENT;
    float s = 0.f;
#pragma unroll
    for (int i = 0; i < 4; i++) {
        float4 v = p[lane + 32 * i];
        s += v.x * v.x + v.y * v.y + v.z * v.z + v.w * v.w;
        uint2 u;
        u.x = h2u(__floats2half2_rn(v.x, v.y));
        u.y = h2u(__floats2half2_rn(v.z, v.w));
        *(uint2*)(drow + (lane + 32 * i) * 4) = u;
    }
#pragma unroll
    for (int o = 16; o; o >>= 1) s += __shfl_xor_sync(0xFFFFFFFFu, s, o);
    if (!lane) nrm[w] = s;
}

__global__ void prep_all(const float* __restrict__ x, const float* __restrict__ sub,
                         const float* __restrict__ sup) {
    int b = blockIdx.x, tid = threadIdx.x;
    int wv = tid >> 5, lane = tid & 31;
    if (b < 4096) {
        conv_row(x, g_Ah, g_xx, b * 8 + wv, lane);
    } else if (b < 4224) {
        conv_row(sub, g_Bh, g_yysub, (b - 4096) * 8 + wv, lane);
    } else if (b < 4256) {
        int w = (b - 4224) * 8 + wv;
        const float4* p = (const float4*)(sup + (size_t)w * LATENT);
        float s = 0.f;
#pragma unroll
        for (int i = 0; i < 4; i++) {
            float4 v = p[lane + 32 * i];
            s += v.x * v.x + v.y * v.y + v.z * v.z + v.w * v.w;
        }
#pragma unroll
        for (int o = 16; o; o >>= 1) s += __shfl_xor_sync(0xFFFFFFFFu, s, o);
        if (!lane) g_yysup[w] = s;
    } else {
        int t = (b - 4256) * 256 + tid;            // 32768 threads
        g_rowmin[t] = INF_KEY;
        if (t < NSUB)  { g_colmin[t] = INF_KEY; g_sscol[t] = INF_KEY; }
        if (t < NSUP)  g_ssrow[t] = INF_KEY;
        if (t < 56 * LATENT) {
            int r = t / LATENT, k = t % LATENT;
            g_Bh[(size_t)(M2BASE + NOUT + r) * LATENT + k] = __float2half(0.f);
            g_Bh[(size_t)(M1BASE + NOUT + r) * LATENT + k] = __float2half(0.f);
        }
    }
}

// ------------------------- fused mid kernel ----------------------------------
// grid 1010 x 256:
//   [0,416)    : buildM2 (sub, W2)    32 x 13 tiles
//   [416,832)  : buildM1 (sup, W1)
//   [832,882)  : svec (8 warps/block, 400 warps)
//   [882,1010) : supersub (32 x 4)
__device__ void buildM_body(const float* __restrict__ P, const float* __restrict__ W,
                            int J, int rowbase, int bb) {
    __shared__ float sP[64][17];
    __shared__ float sW[16][65];
    int k0 = (bb & 31) * 16, o0 = (bb >> 5) * 16;
    int tid = threadIdx.x;
    int tx = tid & 15, ty = tid >> 4;
    float acc = 0.f;
    for (int j0 = 0; j0 < J; j0 += 64) {
        for (int i = tid; i < 64 * 16; i += 256) {
            int jj = i / 16, kk = i % 16;
            sP[jj][kk] = P[(size_t)(j0 + jj) * LATENT + k0 + kk];
        }
        for (int i = tid; i < 16 * 64; i += 256) {
            int oo = i / 64, jj = i % 64;
            int o = o0 + oo;
            sW[oo][jj] = (o < NOUT) ? W[(size_t)o * J + j0 + jj] : 0.f;
        }
        __syncthreads();
#pragma unroll 16
        for (int jj = 0; jj < 64; jj++) acc += sP[jj][tx] * sW[ty][jj];
        __syncthreads();
    }
    if (o0 + ty < NOUT)
        g_Bh[(size_t)(rowbase + o0 + ty) * LATENT + k0 + tx] = __float2half_rn(acc);
}

__device__ void svec_body(const float* __restrict__ W1, const float* __restrict__ b1,
                          const float* __restrict__ W2, const float* __restrict__ b2,
                          int bb) {
    int w = bb * 8 + (threadIdx.x >> 5);
    int lane = threadIdx.x & 31;
    if (w >= 2 * NOUT) return;
    const float *W, *b, *yy;
    float *s, *c;
    int J, o;
    if (w < NOUT) { o = w;        W = W1; b = b1; yy = g_yysup; s = g_s1; c = g_c1; J = NSUP; }
    else          { o = w - NOUT; W = W2; b = b2; yy = g_yysub; s = g_s2; c = g_c2; J = NSUB; }
    float sw = 0.f, cy = 0.f;
    for (int j = lane; j < J; j += 32) {
        float wv = W[(size_t)o * J + j];
        sw += wv;
        cy += yy[j] * wv;
    }
#pragma unroll
    for (int off = 16; off; off >>= 1) {
        sw += __shfl_xor_sync(0xFFFFFFFFu, sw, off);
        cy += __shfl_xor_sync(0xFFFFFFFFu, cy, off);
    }
    if (!lane) { s[o] = sw; c[o] = b[o] + cy; }
}

__device__ void supersub_body(const float* __restrict__ sup, const float* __restrict__ sub,
                              int bb) {
    __shared__ float4 sp[8][LATENT / 4];
    __shared__ float  red[256];
    int i0 = (bb & 31) * 8, tid = threadIdx.x;
    int j = (bb >> 5) * 256 + tid;
    for (int t = tid; t < 8 * (LATENT / 4); t += 256) {
        int r = t / (LATENT / 4), k = t % (LATENT / 4);
        sp[r][k] = ((const float4*)(sup + (size_t)(i0 + r) * LATENT))[k];
    }
    __syncthreads();

    const float4* pj = (const float4*)(sub + (size_t)j * LATENT);
    float dot[8];
#pragma unroll
    for (int r = 0; r < 8; r++) dot[r] = 0.f;
    for (int k = 0; k < LATENT / 4; k++) {
        float4 p = pj[k];
#pragma unroll
        for (int r = 0; r < 8; r++) {
            float4 a = sp[r][k];
            dot[r] += a.x * p.x + a.y * p.y + a.z * p.z + a.w * p.w;
        }
    }
    float yj = g_yysub[j], cmin = 3.4e38f;
    float dr[8];
#pragma unroll
    for (int r = 0; r < 8; r++) {
        dr[r] = g_yysup[i0 + r] - 2.f * dot[r] + yj;
        cmin = fminf(cmin, dr[r]);
    }
    atomicMin(&g_sscol[j], fkey(cmin));
#pragma unroll
    for (int r = 0; r < 8; r++) {
        red[tid] = dr[r];
        __syncthreads();
        for (int s = 128; s; s >>= 1) {
            if (tid < s) red[tid] = fminf(red[tid], red[tid + s]);
            __syncthreads();
        }
        if (tid == 0) atomicMin(&g_ssrow[i0 + r], fkey(red[0]));
        __syncthreads();
    }
}

__global__ void mid_all(const float* __restrict__ sub, const float* __restrict__ sup,
                        const float* __restrict__ W1, const float* __restrict__ b1,
                        const float* __restrict__ W2, const float* __restrict__ b2) {
    int b = blockIdx.x;
    if (b < 416)       buildM_body(sub, W2, NSUB, M2BASE, b);
    else if (b < 832)  buildM_body(sup, W1, NSUP, M1BASE, b - 416);
    else if (b < 882)  svec_body(W1, b1, W2, b2, b - 832);
    else               supersub_body(sup, sub, b - 882);
}

// ------------------------------- main GEMM (mma.sync fp16) -------------------
// grid (6, 256). 512 threads = 16 warps: wm = wid&3 (rows 32), wn = wid>>2 (cols 64).
// Warp tile 32x64. KC=64, 3 stages, ONE barrier per k-iter.
__device__ __forceinline__ void load_chunk(uint32_t astage, const __half* Abase,
                                           const __half* Bbase, int k0, int tid) {
#pragma unroll
    for (int t = 0; t < 2; t++) {            // A: 128 rows x 8 x 16B = 1024 segs
        int seg = tid + t * NTHREADS;
        int row = seg >> 3, q = seg & 7;
        cp16(astage + row * (ROWSTR_H * 2) + q * 16,
             Abase + (size_t)row * LATENT + k0 + q * 8);
    }
    uint32_t bstage = astage + ABYTES;
#pragma unroll
    for (int t = 0; t < 4; t++) {            // B: 256 rows x 8 x 16B = 2048 segs
        int seg = tid + t * NTHREADS;
        int row = seg >> 3, q = seg & 7;
        cp16(bstage + row * (ROWSTR_H * 2) + q * 16,
             Bbase + (size_t)row * LATENT + k0 + q * 8);
    }
}

__global__ __launch_bounds__(NTHREADS) void gemm_tc(
    float* __restrict__ outSub, float* __restrict__ outSup)
{
    extern __shared__ char dyn[];
    __shared__ unsigned s_row[MTILE], s_col[NTILE];
    __shared__ float sh_c0[NTILE], sh_c1[NTILE];

    const int tid = threadIdx.x;
    const int wid = tid >> 5, lane = tid & 31;
    const int grp = lane >> 2, tig = lane & 3;
    const int wm = wid & 3, wn = wid >> 2;
    const int bn = blockIdx.x, bm = blockIdx.y;
    const uint32_t dynb = smem_u32(dyn);

    if (tid < MTILE) s_row[tid] = INF_KEY;
    if (tid < NTILE) {
        s_col[tid] = INF_KEY;
        if (bn < 4) {
            sh_c0[tid] = g_yysub[bn * NTILE + tid];
        } else {
            const float* sv = (bn == 4) ? g_s2 : g_s1;
            const float* cv = (bn == 4) ? g_c2 : g_c1;
            sh_c0[tid] = (tid < NOUT) ? sv[tid] : 0.f;
            sh_c1[tid] = (tid < NOUT) ? cv[tid] : 0.f;
        }
    }

    const __half* Abase = g_Ah + (size_t)bm * MTILE * LATENT;
    const __half* Bbase = g_Bh + (size_t)bn * NTILE * LATENT;

    // prologue: stages 0,1
#pragma unroll
    for (int s = 0; s < NSTAGES - 1; s++) {
        load_chunk(dynb + s * STAGE_BYTES, Abase, Bbase, s * KC, tid);
        CP_COMMIT();
    }

    float acc[2][8][4];
#pragma unroll
    for (int mf = 0; mf < 2; mf++)
#pragma unroll
        for (int nf = 0; nf < 8; nf++)
#pragma unroll
            for (int e = 0; e < 4; e++) acc[mf][nf][e] = 0.f;

    // ldmatrix lane address offsets (in halves)
    const int a_moff = ((lane >> 3) & 1) * 8 + (lane & 7);
    const int a_koff = (lane >> 4) * 8;
    const int b_noff = (lane >> 4) * 8 + (lane & 7);
    const int b_koff = ((lane >> 3) & 1) * 8;

    int stage = 0;
    for (int k = 0; k < KITERS; k++) {
        CP_WAIT1();
        __syncthreads();
        // prefetch into the stage freed at iter k-1 (barrier above guarantees safety)
        if (k + NSTAGES - 1 < KITERS) {
            int ps = stage + 2;
            if (ps >= NSTAGES) ps -= NSTAGES;
            load_chunk(dynb + ps * STAGE_BYTES, Abase, Bbase, (k + NSTAGES - 1) * KC, tid);
        }
        CP_COMMIT();

        const uint32_t As = dynb + stage * STAGE_BYTES;
        const uint32_t Bs = As + ABYTES;
#pragma unroll
        for (int ks = 0; ks < 4; ks++) {
            const int kb = ks * 16;
            uint32_t a[2][4], b[8][2];
            {
                uint32_t addr = As + (uint32_t)(((wm * 32 + a_moff) * ROWSTR_H
                                                 + kb + a_koff) * 2);
                ldsm4(a[0][0], a[0][1], a[0][2], a[0][3], addr);
                addr = As + (uint32_t)(((wm * 32 + 16 + a_moff) * ROWSTR_H
                                         + kb + a_koff) * 2);
                ldsm4(a[1][0], a[1][1], a[1][2], a[1][3], addr);
            }
#pragma unroll
            for (int nfp = 0; nfp < 4; nfp++) {
                uint32_t addr = Bs + (uint32_t)(((wn * 64 + nfp * 16 + b_noff) * ROWSTR_H
                                                 + kb + b_koff) * 2);
                ldsm4(b[2 * nfp][0], b[2 * nfp][1], b[2 * nfp + 1][0], b[2 * nfp + 1][1], addr);
            }
#pragma unroll
            for (int mf = 0; mf < 2; mf++)
#pragma unroll
                for (int nf = 0; nf < 8; nf++)
                    mma16816(acc[mf][nf], a[mf], b[nf]);
        }
        if (++stage == NSTAGES) stage = 0;
    }

    // ------------------------------ epilogue ---------------------------------
    float xr[2][2];
#pragma unroll
    for (int mf = 0; mf < 2; mf++)
#pragma unroll
        for (int h = 0; h < 2; h++)
            xr[mf][h] = g_xx[bm * MTILE + wm * 32 + mf * 16 + h * 8 + grp];

    if (bn < 4) {                                      // distance region
#pragma unroll
        for (int mf = 0; mf < 2; mf++)
#pragma unroll
            for (int nf = 0; nf < 8; nf++) {
                float y0 = sh_c0[wn * 64 + nf * 8 + tig * 2];
                float y1 = sh_c0[wn * 64 + nf * 8 + tig * 2 + 1];
                acc[mf][nf][0] = xr[mf][0] - 2.f * acc[mf][nf][0] + y0;
                acc[mf][nf][1] = xr[mf][0] - 2.f * acc[mf][nf][1] + y1;
                acc[mf][nf][2] = xr[mf][1] - 2.f * acc[mf][nf][2] + y0;
                acc[mf][nf][3] = xr[mf][1] - 2.f * acc[mf][nf][3] + y1;
            }
        // row mins
#pragma unroll
        for (int mf = 0; mf < 2; mf++)
#pragma unroll
            for (int h = 0; h < 2; h++) {
                float m = 3.4e38f;
#pragma unroll
                for (int nf = 0; nf < 8; nf++)
                    m = fminf(m, fminf(acc[mf][nf][h * 2], acc[mf][nf][h * 2 + 1]));
                m = fminf(m, __shfl_xor_sync(0xFFFFFFFFu, m, 1));
                m = fminf(m, __shfl_xor_sync(0xFFFFFFFFu, m, 2));
                if (tig == 0)
                    atomicMin(&s_row[wm * 32 + mf * 16 + h * 8 + grp], fkey(m));
            }
        // col mins
#pragma unroll
        for (int nf = 0; nf < 8; nf++)
#pragma unroll
            for (int c = 0; c < 2; c++) {
                float m = 3.4e38f;
#pragma unroll
                for (int mf = 0; mf < 2; mf++)
                    m = fminf(m, fminf(acc[mf][nf][c], acc[mf][nf][2 + c]));
                m = fminf(m, __shfl_xor_sync(0xFFFFFFFFu, m, 4));
                m = fminf(m, __shfl_xor_sync(0xFFFFFFFFu, m, 8));
                m = fminf(m, __shfl_xor_sync(0xFFFFFFFFu, m, 16));
                if (grp == 0)
                    atomicMin(&s_col[wn * 64 + nf * 8 + tig * 2 + c], fkey(m));
            }
        __syncthreads();
        if (tid < MTILE) atomicMin(&g_rowmin[bm * MTILE + tid], s_row[tid]);
        if (tid < NTILE) atomicMin(&g_colmin[bn * NTILE + tid], s_col[tid]);
    } else {                                           // linear output regions
        float* outp = (bn == 4) ? outSub : outSup;
#pragma unroll
        for (int mf = 0; mf < 2; mf++)
#pragma unroll
            for (int h = 0; h < 2; h++) {
                int row = bm * MTILE + wm * 32 + mf * 16 + h * 8 + grp;
                float xv = xr[mf][h];
#pragma unroll
                for (int nf = 0; nf < 8; nf++) {
                    int o = wn * 64 + nf * 8 + tig * 2;
                    if (o < NOUT) {
                        float2 v;
                        v.x = xv * sh_c0[o]     - 2.f * acc[mf][nf][h * 2]     + sh_c1[o];
                        v.y = xv * sh_c0[o + 1] - 2.f * acc[mf][nf][h * 2 + 1] + sh_c1[o + 1];
                        *(float2*)(outp + (size_t)row * NOUT + o) = v;
                    }
                }
            }
    }
}

// -------------------- finalize stage 1: rowmin partial sums -------------------
// grid 32 x 1024: block b tree-reduces rowmin[b*1024 .. b*1024+1023] -> g_psum[b]
__global__ void finalize_part() {
    __shared__ float red[1024];
    int tid = threadIdx.x;
    red[tid] = funkey(g_rowmin[blockIdx.x * 1024 + tid]);
    __syncthreads();
    for (int s = 512; s > 0; s >>= 1) {
        if (tid < s) red[tid] += red[tid + s];
        __syncthreads();
    }
    if (tid == 0) g_psum[blockIdx.x] = red[0];
}

// -------------------- finalize stage 2: r1..r4 --------------------------------
__global__ void finalize_last(float* __restrict__ out4) {
    __shared__ float red[1024];
    int tid = threadIdx.x;
    float r1 = 0.f, r2 = 0.f, r3 = 0.f;

    red[tid] = funkey(g_colmin[tid]);
    __syncthreads();
    for (int s = 512; s > 0; s >>= 1) { if (tid < s) red[tid] += red[tid + s]; __syncthreads(); }
    if (tid == 0) r1 = red[0] * (1.f / NSUB);
    __syncthreads();

    red[tid] = (tid < 32) ? g_psum[tid] : 0.f;
    __syncthreads();
    for (int s = 512; s > 0; s >>= 1) { if (tid < s) red[tid] += red[tid + s]; __syncthreads(); }
    if (tid == 0) r2 = red[0] * (1.f / BATCH);
    __syncthreads();

    red[tid] = (tid < NSUP) ? funkey(g_ssrow[tid]) : 0.f;
    __syncthreads();
    for (int s = 512; s > 0; s >>= 1) { if (tid < s) red[tid] += red[tid + s]; __syncthreads(); }
    if (tid == 0) r3 = red[0] * (1.f / NSUP);
    __syncthreads();

    red[tid] = funkey(g_sscol[tid]);
    __syncthreads();
    for (int s = 512; s > 0; s >>= 1) { if (tid < s) red[tid] += red[tid + s]; __syncthreads(); }
    if (tid == 0) {
        out4[0] = r1; out4[1] = r2; out4[2] = r3;
        out4[3] = red[0] * (1.f / NSUB);
    }
}

// ------------------------------- launcher ------------------------------------
extern "C" void kernel_launch(void* const* d_in, const int* in_sizes, int n_in,
                              void* d_out, int out_size) {
    const float* x   = (const float*)d_in[0];
    const float* sup = (const float*)d_in[1];
    const float* sub = (const float*)d_in[2];
    const float* W1  = (const float*)d_in[3];
    const float* b1  = (const float*)d_in[4];
    const float* W2  = (const float*)d_in[5];
    const float* b2  = (const float*)d_in[6];
    float* out    = (float*)d_out;
    float* outSub = out;
    float* outSup = out + (size_t)BATCH * NOUT;
    float* out4   = out + (size_t)2 * BATCH * NOUT;

    cudaFuncSetAttribute(gemm_tc, cudaFuncAttributeMaxDynamicSharedMemorySize, SMEM_DYN);

    prep_all<<<4384, 256>>>(x, sub, sup);
    mid_all<<<1010, 256>>>(sub, sup, W1, b1, W2, b2);
    gemm_tc<<<dim3(BROWS / NTILE, BATCH / MTILE), NTHREADS, SMEM_DYN>>>(outSub, outSup);
    finalize_part<<<32, 1024>>>();
    finalize_last<<<1, 1024>>>(out4);
}